// round 1
// baseline (speedup 1.0000x reference)
#include <cuda_runtime.h>

// ============================================================================
// spectralNNDeepshared2: MLP (sigmoid) chain + sliding-window contraction.
// Round 0: fp32 SIMT baseline using packed fma.rn.f32x2 (FFMA2) microkernel.
//
// Shapes: M=64, N=4096, D=64, WIDTH=256, DEPTH=4, WIN=65, BATCH=1024.
//   u1      = sig(W0[m] (256x64) @ uT (64x1024))           per m
//   u1      = sig(W[i][m] (256x256) @ u1)   x3             per m
//   G[m]    = sig(Wf[m] (65x256) @ u1)                     per m
//   out[n,b]= sum_{m,j} xi[m, n+j] * G[m,j,b]
//           = A (4096x4160) @ G (4160x1024), A[n,k]=xi[m,n+j], k=m*65+j
// ============================================================================

#define BM 128
#define BN 128
#define BK 8
#define TM 8
#define TNH 4  // 8 output cols per thread as 4 f32x2 pairs

// Scratch (static device allocations; allocation inside kernel_launch is banned)
__device__ float g_uT[64 * 1024];                 // 256 KB
__device__ float g_bufA[64 * 256 * 1024];         // 64 MB
__device__ float g_bufB[64 * 256 * 1024];         // 64 MB
__device__ float g_G[4160 * 1024];                // 17 MB

__device__ __forceinline__ unsigned long long pack2(float x, float y) {
    unsigned long long r;
    asm("mov.b64 %0, {%1, %2};" : "=l"(r)
        : "r"(__float_as_uint(x)), "r"(__float_as_uint(y)));
    return r;
}
__device__ __forceinline__ void unpack2(unsigned long long v, float& x, float& y) {
    unsigned int lo, hi;
    asm("mov.b64 {%0, %1}, %2;" : "=r"(lo), "=r"(hi) : "l"(v));
    x = __uint_as_float(lo);
    y = __uint_as_float(hi);
}
__device__ __forceinline__ void ffma2(unsigned long long& acc,
                                      unsigned long long a, unsigned long long b) {
    asm("fma.rn.f32x2 %0, %1, %2, %0;" : "+l"(acc) : "l"(a), "l"(b));
}

__device__ __forceinline__ float sigmoidf_fast(float x) {
    return 1.0f / (1.0f + __expf(-x));
}

// ----------------------------------------------------------------------------
// Transpose u (1024x64) -> uT (64x1024)
// ----------------------------------------------------------------------------
__global__ void transpose_u_kernel(const float* __restrict__ u, float* __restrict__ uT) {
    __shared__ float t[32][33];
    int b0 = blockIdx.x * 32;
    int d0 = blockIdx.y * 32;
    int x = threadIdx.x, y = threadIdx.y;
    t[y][x] = u[(long)(b0 + y) * 64 + (d0 + x)];
    __syncthreads();
    uT[(long)(d0 + y) * 1024 + (b0 + x)] = t[x][y];
}

// ----------------------------------------------------------------------------
// Batched (over m) GEMM + bias + sigmoid:  C[m] = sig(A[m] @ B[m] + bias[m])
// A: rows x K row-major, B: K x 1024 row-major, C: rows x 1024
// ----------------------------------------------------------------------------
__global__ __launch_bounds__(256) void mlp_gemm_kernel(
    const float* __restrict__ A_all, long aStride,
    const float* __restrict__ B_all, long bStride,
    float* __restrict__ C_all, long cStride,
    const float* __restrict__ bias_all, int biasStride,
    int rows, int K, int doSig)
{
    __shared__ float As[BK][BM + 1];
    __shared__ __align__(16) float Bs[BK][BN];

    const int m = blockIdx.z;
    const float* A = A_all + (long)m * aStride;
    const float* B = B_all + (long)m * bStride;
    float* C = C_all + (long)m * cStride;
    const float* bias = bias_all + (long)m * biasStride;

    const int row0 = blockIdx.y * BM;
    const int col0 = blockIdx.x * BN;
    const int tid = threadIdx.x;
    const int trow = (tid >> 4) * TM;
    const int tcol = (tid & 15) * (2 * TNH);

    unsigned long long acc[TM][TNH] = {};

    for (int k0 = 0; k0 < K; k0 += BK) {
        // A tile (BM x BK): consecutive tids walk k fastest -> 32B-sector coalesced
        #pragma unroll
        for (int i = 0; i < 4; i++) {
            int idx = tid + i * 256;
            int r = idx >> 3;
            int kk = idx & 7;
            int gr = row0 + r;
            As[kk][r] = (gr < rows) ? A[(long)gr * K + (k0 + kk)] : 0.0f;
        }
        // B tile (BK x BN): 128-float contiguous rows, fully coalesced
        #pragma unroll
        for (int i = 0; i < 4; i++) {
            int idx = tid + i * 256;
            int kk = idx >> 7;
            int c = idx & 127;
            Bs[kk][c] = B[(long)(k0 + kk) * 1024 + (col0 + c)];
        }
        __syncthreads();

        #pragma unroll
        for (int kk = 0; kk < BK; kk++) {
            unsigned long long bP[TNH];
            #pragma unroll
            for (int j = 0; j < TNH; j++) {
                float2 b2 = *reinterpret_cast<const float2*>(&Bs[kk][tcol + 2 * j]);
                bP[j] = pack2(b2.x, b2.y);
            }
            #pragma unroll
            for (int i = 0; i < TM; i++) {
                float a = As[kk][trow + i];
                unsigned long long a2 = pack2(a, a);
                #pragma unroll
                for (int j = 0; j < TNH; j++) ffma2(acc[i][j], a2, bP[j]);
            }
        }
        __syncthreads();
    }

    #pragma unroll
    for (int i = 0; i < TM; i++) {
        int gr = row0 + trow + i;
        if (gr >= rows) continue;
        float bv = bias[gr];
        #pragma unroll
        for (int j = 0; j < TNH; j++) {
            float x0, x1;
            unpack2(acc[i][j], x0, x1);
            x0 += bv;
            x1 += bv;
            if (doSig) {
                x0 = sigmoidf_fast(x0);
                x1 = sigmoidf_fast(x1);
            }
            *reinterpret_cast<float2*>(&C[(long)gr * 1024 + col0 + tcol + 2 * j]) =
                make_float2(x0, x1);
        }
    }
}

// ----------------------------------------------------------------------------
// Output contraction: C (4096x1024) = A (4096x4160) @ G (4160x1024)
// A[n,k] = xi[m, n + j] with m = k/65, j = k%65 (gathered on the fly)
// ----------------------------------------------------------------------------
__global__ __launch_bounds__(256) void out_gemm_kernel(
    const float* __restrict__ xi,   // 64 x 4160
    const float* __restrict__ G,    // 4160 x 1024
    float* __restrict__ C)          // 4096 x 1024
{
    __shared__ float As[BK][BM + 1];
    __shared__ __align__(16) float Bs[BK][BN];

    const int n0 = blockIdx.y * BM;
    const int col0 = blockIdx.x * BN;
    const int tid = threadIdx.x;
    const int trow = (tid >> 4) * TM;
    const int tcol = (tid & 15) * (2 * TNH);

    unsigned long long acc[TM][TNH] = {};

    for (int k0 = 0; k0 < 4160; k0 += BK) {
        // A tile: for each k-row, 128 consecutive xi values -> coalesced
        #pragma unroll
        for (int i = 0; i < 4; i++) {
            int idx = tid + i * 256;
            int kk = idx >> 7;
            int n = idx & 127;
            int k = k0 + kk;
            int mm = k / 65;
            int j = k - mm * 65;
            As[kk][n] = xi[mm * 4160 + (n0 + n + j)];
        }
        #pragma unroll
        for (int i = 0; i < 4; i++) {
            int idx = tid + i * 256;
            int kk = idx >> 7;
            int c = idx & 127;
            Bs[kk][c] = G[(long)(k0 + kk) * 1024 + (col0 + c)];
        }
        __syncthreads();

        #pragma unroll
        for (int kk = 0; kk < BK; kk++) {
            unsigned long long bP[TNH];
            #pragma unroll
            for (int j = 0; j < TNH; j++) {
                float2 b2 = *reinterpret_cast<const float2*>(&Bs[kk][tcol + 2 * j]);
                bP[j] = pack2(b2.x, b2.y);
            }
            #pragma unroll
            for (int i = 0; i < TM; i++) {
                float a = As[kk][trow + i];
                unsigned long long a2 = pack2(a, a);
                #pragma unroll
                for (int j = 0; j < TNH; j++) ffma2(acc[i][j], a2, bP[j]);
            }
        }
        __syncthreads();
    }

    #pragma unroll
    for (int i = 0; i < TM; i++) {
        int gr = n0 + trow + i;
        #pragma unroll
        for (int j = 0; j < TNH; j++) {
            float x0, x1;
            unpack2(acc[i][j], x0, x1);
            *reinterpret_cast<float2*>(&C[(long)gr * 1024 + col0 + tcol + 2 * j]) =
                make_float2(x0, x1);
        }
    }
}

// ----------------------------------------------------------------------------
// Launch
// ----------------------------------------------------------------------------
extern "C" void kernel_launch(void* const* d_in, const int* in_sizes, int n_in,
                              void* d_out, int out_size) {
    const float* u  = (const float*)d_in[0];  // (1024, 64)
    const float* w0 = (const float*)d_in[1];  // (64, 256, 64)
    const float* b0 = (const float*)d_in[2];  // (64, 256, 1)
    const float* w  = (const float*)d_in[3];  // (3, 64, 256, 256)
    const float* b  = (const float*)d_in[4];  // (3, 64, 256, 1)
    const float* wf = (const float*)d_in[5];  // (64, 65, 256)
    const float* bf = (const float*)d_in[6];  // (64, 65, 1)
    const float* xi = (const float*)d_in[7];  // (64, 4160)
    float* out = (float*)d_out;               // (4096, 1024)

    void* p;
    cudaGetSymbolAddress(&p, g_uT);   float* uT   = (float*)p;
    cudaGetSymbolAddress(&p, g_bufA); float* bufA = (float*)p;
    cudaGetSymbolAddress(&p, g_bufB); float* bufB = (float*)p;
    cudaGetSymbolAddress(&p, g_G);    float* G    = (float*)p;

    dim3 blk(256);

    transpose_u_kernel<<<dim3(32, 2), dim3(32, 32)>>>(u, uT);

    // layer 0: rows=256, K=64, B shared across m (bStride=0)
    mlp_gemm_kernel<<<dim3(8, 2, 64), blk>>>(
        w0, 256L * 64, uT, 0L, bufA, 256L * 1024, b0, 256, 256, 64, 1);

    // 3 hidden layers: rows=256, K=256
    const float* src = bufA;
    float* dst = bufB;
    for (int i = 0; i < 3; i++) {
        mlp_gemm_kernel<<<dim3(8, 2, 64), blk>>>(
            w + (long)i * 64 * 256 * 256, 256L * 256,
            src, 256L * 1024, dst, 256L * 1024,
            b + (long)i * 64 * 256, 256, 256, 256, 1);
        const float* t = src;
        src = dst;
        dst = (float*)t;
    }
    // after 3 iterations result is in bufB (== src)

    // final layer: rows=65, K=256 -> G (64, 65, 1024) == (4160, 1024) row-major
    mlp_gemm_kernel<<<dim3(8, 1, 64), blk>>>(
        wf, 65L * 256, src, 256L * 1024, G, 65L * 1024, bf, 65, 65, 256, 1);

    // sliding-window contraction as one big GEMM
    out_gemm_kernel<<<dim3(8, 32), blk>>>(xi, G, out);
}

// round 3
// speedup vs baseline: 1.4698x; 1.4698x over previous
#include <cuda_runtime.h>
#include <cuda_bf16.h>
#include <cstdint>

// ============================================================================
// spectralNNDeepshared2 — Round 2:
//   MLP chain: fp32 SIMT FFMA2 (unchanged, known-good)
//   Output contraction: mma.sync bf16 split-precision GEMM (compute_103-legal;
//   tcgen05 is unavailable because the harness PTX target lacks the 'a' suffix)
// ============================================================================

#define BM 128
#define BN 128
#define BK 8
#define TM 8
#define TNH 4

// ---------------- scratch ----------------
__device__ float g_uT[64 * 1024];
__device__ float g_bufA[64 * 256 * 1024];
__device__ float g_bufB[64 * 256 * 1024];
__device__ float g_G[4160 * 1024];
__device__ __nv_bfloat16 g_Ahi[4096L * 4160];
__device__ __nv_bfloat16 g_Alo[4096L * 4160];
__device__ __nv_bfloat16 g_Bhi[4160L * 1024];
__device__ __nv_bfloat16 g_Blo[4160L * 1024];

// ---------------- fp32x2 helpers (MLP path) ----------------
__device__ __forceinline__ unsigned long long pack2(float x, float y) {
    unsigned long long r;
    asm("mov.b64 %0, {%1, %2};" : "=l"(r)
        : "r"(__float_as_uint(x)), "r"(__float_as_uint(y)));
    return r;
}
__device__ __forceinline__ void unpack2(unsigned long long v, float& x, float& y) {
    unsigned int lo, hi;
    asm("mov.b64 {%0, %1}, %2;" : "=r"(lo), "=r"(hi) : "l"(v));
    x = __uint_as_float(lo);
    y = __uint_as_float(hi);
}
__device__ __forceinline__ void ffma2(unsigned long long& acc,
                                      unsigned long long a, unsigned long long b) {
    asm("fma.rn.f32x2 %0, %1, %2, %0;" : "+l"(acc) : "l"(a), "l"(b));
}
__device__ __forceinline__ float sigmoidf_fast(float x) {
    return 1.0f / (1.0f + __expf(-x));
}

__device__ __forceinline__ uint32_t smem_u32(const void* p) {
    uint32_t a;
    asm("{ .reg .u64 t; cvta.to.shared.u64 t, %1; cvt.u32.u64 %0, t; }"
        : "=r"(a) : "l"(p));
    return a;
}

// ---------------- cp.async / ldmatrix / mma helpers ----------------
__device__ __forceinline__ void cp16(uint32_t dst, const void* src) {
    asm volatile("cp.async.cg.shared.global [%0], [%1], 16;\n"
                 :: "r"(dst), "l"(src));
}
#define CP_COMMIT() asm volatile("cp.async.commit_group;\n" ::: "memory")
#define CP_WAIT(n)  asm volatile("cp.async.wait_group %0;\n" :: "n"(n) : "memory")

__device__ __forceinline__ void ldsm_x4(uint32_t* r, uint32_t addr) {
    asm volatile("ldmatrix.sync.aligned.m8n8.x4.shared.b16 {%0,%1,%2,%3}, [%4];"
        : "=r"(r[0]), "=r"(r[1]), "=r"(r[2]), "=r"(r[3]) : "r"(addr));
}
__device__ __forceinline__ void ldsm_x4t(uint32_t* r, uint32_t addr) {
    asm volatile("ldmatrix.sync.aligned.m8n8.x4.trans.shared.b16 {%0,%1,%2,%3}, [%4];"
        : "=r"(r[0]), "=r"(r[1]), "=r"(r[2]), "=r"(r[3]) : "r"(addr));
}
__device__ __forceinline__ void mma_bf16(float* d, const uint32_t* a, const uint32_t* b) {
    asm volatile(
        "mma.sync.aligned.m16n8k16.row.col.f32.bf16.bf16.f32 "
        "{%0,%1,%2,%3}, {%4,%5,%6,%7}, {%8,%9}, {%0,%1,%2,%3};"
        : "+f"(d[0]), "+f"(d[1]), "+f"(d[2]), "+f"(d[3])
        : "r"(a[0]), "r"(a[1]), "r"(a[2]), "r"(a[3]), "r"(b[0]), "r"(b[1]));
}

// ----------------------------------------------------------------------------
// Transpose u (1024x64) -> uT (64x1024)
// ----------------------------------------------------------------------------
__global__ void transpose_u_kernel(const float* __restrict__ u, float* __restrict__ uT) {
    __shared__ float t[32][33];
    int b0 = blockIdx.x * 32;
    int d0 = blockIdx.y * 32;
    int x = threadIdx.x, y = threadIdx.y;
    t[y][x] = u[(long)(b0 + y) * 64 + (d0 + x)];
    __syncthreads();
    uT[(long)(d0 + y) * 1024 + (b0 + x)] = t[x][y];
}

// ----------------------------------------------------------------------------
// Batched (over m) GEMM + bias + sigmoid (fp32 SIMT, FFMA2)
// ----------------------------------------------------------------------------
__global__ __launch_bounds__(256) void mlp_gemm_kernel(
    const float* __restrict__ A_all, long aStride,
    const float* __restrict__ B_all, long bStride,
    float* __restrict__ C_all, long cStride,
    const float* __restrict__ bias_all, int biasStride,
    int rows, int K, int doSig)
{
    __shared__ float As[BK][BM + 1];
    __shared__ __align__(16) float Bs[BK][BN];

    const int m = blockIdx.z;
    const float* A = A_all + (long)m * aStride;
    const float* B = B_all + (long)m * bStride;
    float* C = C_all + (long)m * cStride;
    const float* bias = bias_all + (long)m * biasStride;

    const int row0 = blockIdx.y * BM;
    const int col0 = blockIdx.x * BN;
    const int tid = threadIdx.x;
    const int trow = (tid >> 4) * TM;
    const int tcol = (tid & 15) * (2 * TNH);

    unsigned long long acc[TM][TNH] = {};

    for (int k0 = 0; k0 < K; k0 += BK) {
        #pragma unroll
        for (int i = 0; i < 4; i++) {
            int idx = tid + i * 256;
            int r = idx >> 3;
            int kk = idx & 7;
            int gr = row0 + r;
            As[kk][r] = (gr < rows) ? A[(long)gr * K + (k0 + kk)] : 0.0f;
        }
        #pragma unroll
        for (int i = 0; i < 4; i++) {
            int idx = tid + i * 256;
            int kk = idx >> 7;
            int c = idx & 127;
            Bs[kk][c] = B[(long)(k0 + kk) * 1024 + (col0 + c)];
        }
        __syncthreads();

        #pragma unroll
        for (int kk = 0; kk < BK; kk++) {
            unsigned long long bP[TNH];
            #pragma unroll
            for (int j = 0; j < TNH; j++) {
                float2 b2 = *reinterpret_cast<const float2*>(&Bs[kk][tcol + 2 * j]);
                bP[j] = pack2(b2.x, b2.y);
            }
            #pragma unroll
            for (int i = 0; i < TM; i++) {
                float a = As[kk][trow + i];
                unsigned long long a2 = pack2(a, a);
                #pragma unroll
                for (int j = 0; j < TNH; j++) ffma2(acc[i][j], a2, bP[j]);
            }
        }
        __syncthreads();
    }

    #pragma unroll
    for (int i = 0; i < TM; i++) {
        int gr = row0 + trow + i;
        if (gr >= rows) continue;
        float bv = bias[gr];
        #pragma unroll
        for (int j = 0; j < TNH; j++) {
            float x0, x1;
            unpack2(acc[i][j], x0, x1);
            x0 += bv;
            x1 += bv;
            if (doSig) {
                x0 = sigmoidf_fast(x0);
                x1 = sigmoidf_fast(x1);
            }
            *reinterpret_cast<float2*>(&C[(long)gr * 1024 + col0 + tcol + 2 * j]) =
                make_float2(x0, x1);
        }
    }
}

// ----------------------------------------------------------------------------
// Build sliding-window A matrix (4096 x 4160) as bf16 hi/lo split
// A[n,k] = xi[m, n + j], m = k/65, j = k%65
// ----------------------------------------------------------------------------
__global__ void build_A_kernel(const float* __restrict__ xi,
                               __nv_bfloat16* __restrict__ Ahi,
                               __nv_bfloat16* __restrict__ Alo)
{
    int n = blockIdx.x;
    for (int k = threadIdx.x; k < 4160; k += 256) {
        int m = k / 65;
        int j = k - m * 65;
        float v = xi[m * 4160 + n + j];
        __nv_bfloat16 h = __float2bfloat16(v);
        float lo = v - __bfloat162float(h);
        Ahi[(long)n * 4160 + k] = h;
        Alo[(long)n * 4160 + k] = __float2bfloat16(lo);
    }
}

// ----------------------------------------------------------------------------
// Split G (4160 x 1024 fp32, row-major) -> Bhi/Blo bf16 (same layout)
// ----------------------------------------------------------------------------
__global__ void build_B_kernel(const float* __restrict__ G,
                               __nv_bfloat16* __restrict__ Bhi,
                               __nv_bfloat16* __restrict__ Blo)
{
    long base = (long)blockIdx.x * 1024 + threadIdx.x * 4;
    #pragma unroll
    for (int j = 0; j < 4; j++) {
        float v = G[base + j];
        __nv_bfloat16 h = __float2bfloat16(v);
        Bhi[base + j] = h;
        Blo[base + j] = __float2bfloat16(v - __bfloat162float(h));
    }
}

// ----------------------------------------------------------------------------
// Output GEMM via mma.sync bf16 split precision:
//   out (4096 x 1024) = A (4096 x 4160) @ B (4160 x 1024)
// CTA tile 128x128, K-chunk 32, 8 warps (4m x 2n), warp tile 32x64.
// Double-buffered cp.async smem pipeline; padded strides for conflict-free
// ldmatrix (A: 80B/row, B: 272B/row).
// ----------------------------------------------------------------------------
#define ASTRIDE 80
#define BSTRIDE 272
#define A_TILE  (128 * ASTRIDE)              // 10240 B
#define B_TILE  (32 * BSTRIDE)               // 8704 B
#define STAGE   (2 * A_TILE + 2 * B_TILE)    // 37888 B
#define OUT_SMEM_TOTAL (2 * STAGE)           // 75776 B
#define OFF_AH  0
#define OFF_AL  A_TILE
#define OFF_BH  (2 * A_TILE)
#define OFF_BL  (2 * A_TILE + B_TILE)

__device__ __forceinline__ void load_stage(
    uint32_t sbase,
    const __nv_bfloat16* __restrict__ Ahi, const __nv_bfloat16* __restrict__ Alo,
    const __nv_bfloat16* __restrict__ Bhi, const __nv_bfloat16* __restrict__ Blo,
    int n0, int col0, int k0, int tid)
{
    // A tiles: 128 rows x 32 cols bf16 = 512 x 16B chunks each
    #pragma unroll
    for (int i = 0; i < 2; i++) {
        int idx = tid + i * 256;
        int r = idx >> 2;
        int c = idx & 3;
        long g = (long)(n0 + r) * 4160 + k0 + c * 8;
        uint32_t d = r * ASTRIDE + c * 16;
        cp16(sbase + OFF_AH + d, Ahi + g);
        cp16(sbase + OFF_AL + d, Alo + g);
    }
    // B tiles: 32 rows x 128 cols bf16 = 512 x 16B chunks each
    #pragma unroll
    for (int i = 0; i < 2; i++) {
        int idx = tid + i * 256;
        int r = idx >> 4;
        int c = idx & 15;
        long g = (long)(k0 + r) * 1024 + col0 + c * 8;
        uint32_t d = r * BSTRIDE + c * 16;
        cp16(sbase + OFF_BH + d, Bhi + g);
        cp16(sbase + OFF_BL + d, Blo + g);
    }
}

__global__ __launch_bounds__(256) void out_mma_kernel(
    const __nv_bfloat16* __restrict__ Ahi, const __nv_bfloat16* __restrict__ Alo,
    const __nv_bfloat16* __restrict__ Bhi, const __nv_bfloat16* __restrict__ Blo,
    float* __restrict__ out)
{
    extern __shared__ char smem[];
    const uint32_t sb = smem_u32(smem);
    const int tid = threadIdx.x;
    const int lane = tid & 31;
    const int wid = tid >> 5;
    const int wm = wid & 3;      // 4 m-warps, 32 rows each
    const int wn = wid >> 2;     // 2 n-warps, 64 cols each
    const int n0 = blockIdx.y * 128;
    const int col0 = blockIdx.x * 128;

    float acc[2][8][4];
    #pragma unroll
    for (int mi = 0; mi < 2; mi++)
        #pragma unroll
        for (int nj = 0; nj < 8; nj++)
            #pragma unroll
            for (int q = 0; q < 4; q++) acc[mi][nj][q] = 0.0f;

    // ldmatrix per-lane offsets
    const int quad = lane >> 3;
    const int r8 = lane & 7;
    const int arow = (quad & 1) * 8 + r8;
    const int akc = quad >> 1;
    const uint32_t aoff = (wm * 32 + arow) * ASTRIDE + akc * 16;
    const int bkrow = (quad & 1) * 8 + r8;
    const int bnc = quad >> 1;
    const uint32_t boff = bkrow * BSTRIDE + (wn * 64 + bnc * 8) * 2;

    load_stage(sb, Ahi, Alo, Bhi, Blo, n0, col0, 0, tid);
    CP_COMMIT();

    for (int t = 0; t < 130; t++) {
        const uint32_t cur = sb + (uint32_t)(t & 1) * STAGE;
        if (t + 1 < 130) {
            load_stage(sb + (uint32_t)((t + 1) & 1) * STAGE,
                       Ahi, Alo, Bhi, Blo, n0, col0, (t + 1) * 32, tid);
            CP_COMMIT();
            CP_WAIT(1);
        } else {
            CP_WAIT(0);
        }
        __syncthreads();

        #pragma unroll
        for (int ks = 0; ks < 2; ks++) {
            uint32_t ah[2][4], al[2][4];
            ldsm_x4(ah[0], cur + OFF_AH + aoff + ks * 32);
            ldsm_x4(ah[1], cur + OFF_AH + aoff + 16 * ASTRIDE + ks * 32);
            ldsm_x4(al[0], cur + OFF_AL + aoff + ks * 32);
            ldsm_x4(al[1], cur + OFF_AL + aoff + 16 * ASTRIDE + ks * 32);

            uint32_t bh[8][2], bl[8][2];
            #pragma unroll
            for (int g = 0; g < 4; g++) {
                uint32_t r[4];
                ldsm_x4t(r, cur + OFF_BH + boff + g * 32 + ks * 16 * BSTRIDE);
                bh[2 * g][0] = r[0];
                bh[2 * g][1] = r[1];
                bh[2 * g + 1][0] = r[2];
                bh[2 * g + 1][1] = r[3];
                ldsm_x4t(r, cur + OFF_BL + boff + g * 32 + ks * 16 * BSTRIDE);
                bl[2 * g][0] = r[0];
                bl[2 * g][1] = r[1];
                bl[2 * g + 1][0] = r[2];
                bl[2 * g + 1][1] = r[3];
            }

            #pragma unroll
            for (int mi = 0; mi < 2; mi++)
                #pragma unroll
                for (int nj = 0; nj < 8; nj++) {
                    mma_bf16(acc[mi][nj], ah[mi], bh[nj]);
                    mma_bf16(acc[mi][nj], ah[mi], bl[nj]);
                    mma_bf16(acc[mi][nj], al[mi], bh[nj]);
                }
        }
        __syncthreads();
    }

    // epilogue: standard m16n8 C fragment mapping
    const int grp = lane >> 2;
    const int qid = lane & 3;
    #pragma unroll
    for (int mi = 0; mi < 2; mi++) {
        int rbase = n0 + wm * 32 + mi * 16;
        #pragma unroll
        for (int nj = 0; nj < 8; nj++) {
            int cn = col0 + wn * 64 + nj * 8 + qid * 2;
            *reinterpret_cast<float2*>(&out[(long)(rbase + grp) * 1024 + cn]) =
                make_float2(acc[mi][nj][0], acc[mi][nj][1]);
            *reinterpret_cast<float2*>(&out[(long)(rbase + grp + 8) * 1024 + cn]) =
                make_float2(acc[mi][nj][2], acc[mi][nj][3]);
        }
    }
}

// ----------------------------------------------------------------------------
// Launch
// ----------------------------------------------------------------------------
extern "C" void kernel_launch(void* const* d_in, const int* in_sizes, int n_in,
                              void* d_out, int out_size) {
    const float* u  = (const float*)d_in[0];
    const float* w0 = (const float*)d_in[1];
    const float* b0 = (const float*)d_in[2];
    const float* w  = (const float*)d_in[3];
    const float* b  = (const float*)d_in[4];
    const float* wf = (const float*)d_in[5];
    const float* bf = (const float*)d_in[6];
    const float* xi = (const float*)d_in[7];
    float* out = (float*)d_out;

    void* p;
    cudaGetSymbolAddress(&p, g_uT);   float* uT   = (float*)p;
    cudaGetSymbolAddress(&p, g_bufA); float* bufA = (float*)p;
    cudaGetSymbolAddress(&p, g_bufB); float* bufB = (float*)p;
    cudaGetSymbolAddress(&p, g_G);    float* G    = (float*)p;
    cudaGetSymbolAddress(&p, g_Ahi);  __nv_bfloat16* Ahi = (__nv_bfloat16*)p;
    cudaGetSymbolAddress(&p, g_Alo);  __nv_bfloat16* Alo = (__nv_bfloat16*)p;
    cudaGetSymbolAddress(&p, g_Bhi);  __nv_bfloat16* Bhi = (__nv_bfloat16*)p;
    cudaGetSymbolAddress(&p, g_Blo);  __nv_bfloat16* Blo = (__nv_bfloat16*)p;

    cudaFuncSetAttribute(out_mma_kernel,
                         cudaFuncAttributeMaxDynamicSharedMemorySize, OUT_SMEM_TOTAL);

    dim3 blk(256);

    transpose_u_kernel<<<dim3(32, 2), dim3(32, 32)>>>(u, uT);

    // A matrix build depends only on xi — launch early
    build_A_kernel<<<4096, 256>>>(xi, Ahi, Alo);

    // layer 0: rows=256, K=64
    mlp_gemm_kernel<<<dim3(8, 2, 64), blk>>>(
        w0, 256L * 64, uT, 0L, bufA, 256L * 1024, b0, 256, 256, 64, 1);

    const float* src = bufA;
    float* dst = bufB;
    for (int i = 0; i < 3; i++) {
        mlp_gemm_kernel<<<dim3(8, 2, 64), blk>>>(
            w + (long)i * 64 * 256 * 256, 256L * 256,
            src, 256L * 1024, dst, 256L * 1024,
            b + (long)i * 64 * 256, 256, 256, 256, 1);
        const float* t = src;
        src = dst;
        dst = (float*)t;
    }

    // final layer: rows=65, K=256 -> G (4160, 1024)
    mlp_gemm_kernel<<<dim3(8, 1, 64), blk>>>(
        wf, 65L * 256, src, 256L * 1024, G, 65L * 1024, bf, 65, 65, 256, 1);

    // split G -> Bhi/Blo (no transpose needed for row.col mma + ldmatrix.trans)
    build_B_kernel<<<4160, 256>>>(G, Bhi, Blo);

    // tensor-core output GEMM: 8 col-tiles x 32 row-tiles = 256 CTAs
    out_mma_kernel<<<dim3(8, 32), 256, OUT_SMEM_TOTAL>>>(Ahi, Alo, Bhi, Blo, out);
}

// round 5
// speedup vs baseline: 2.7291x; 1.8567x over previous
#include <cuda_runtime.h>
#include <cuda_bf16.h>
#include <cstdint>

// ============================================================================
// spectralNNDeepshared2 — Round 3:
//   Everything on mma.sync bf16 split-precision tensor cores:
//     - MLP chain (W @ X + bias, sigmoid) with fused hi/lo split output
//     - final layer writes the out-GEMM B operand directly
//     - out-GEMM unchanged from round 2 (known-good)
// ============================================================================

// ---------------- scratch ----------------
__device__ __nv_bfloat16 g_uThi[64 * 1024];
__device__ __nv_bfloat16 g_uTlo[64 * 1024];
__device__ __nv_bfloat16 g_W0hi[64 * 256 * 64];
__device__ __nv_bfloat16 g_W0lo[64 * 256 * 64];
__device__ __nv_bfloat16 g_Whi[3L * 64 * 256 * 256];
__device__ __nv_bfloat16 g_Wlo[3L * 64 * 256 * 256];
__device__ __nv_bfloat16 g_Wfhi[64 * 65 * 256];
__device__ __nv_bfloat16 g_Wflo[64 * 65 * 256];
__device__ __nv_bfloat16 g_actAhi[64L * 256 * 1024];
__device__ __nv_bfloat16 g_actAlo[64L * 256 * 1024];
__device__ __nv_bfloat16 g_actBhi[64L * 256 * 1024];
__device__ __nv_bfloat16 g_actBlo[64L * 256 * 1024];
__device__ __nv_bfloat16 g_Ahi[4096L * 4160];
__device__ __nv_bfloat16 g_Alo[4096L * 4160];
__device__ __nv_bfloat16 g_Bhi[4160L * 1024];
__device__ __nv_bfloat16 g_Blo[4160L * 1024];

__device__ __forceinline__ float sigmoidf_fast(float x) {
    return 1.0f / (1.0f + __expf(-x));
}
__device__ __forceinline__ uint32_t smem_u32(const void* p) {
    uint32_t a;
    asm("{ .reg .u64 t; cvta.to.shared.u64 t, %1; cvt.u32.u64 %0, t; }"
        : "=r"(a) : "l"(p));
    return a;
}

// ---------------- cp.async / ldmatrix / mma helpers ----------------
__device__ __forceinline__ void cp16(uint32_t dst, const void* src) {
    asm volatile("cp.async.cg.shared.global [%0], [%1], 16;\n"
                 :: "r"(dst), "l"(src));
}
__device__ __forceinline__ void cp16z(uint32_t dst, const void* src, bool valid) {
    int sz = valid ? 16 : 0;
    asm volatile("cp.async.cg.shared.global [%0], [%1], 16, %2;\n"
                 :: "r"(dst), "l"(src), "r"(sz));
}
#define CP_COMMIT() asm volatile("cp.async.commit_group;\n" ::: "memory")
#define CP_WAIT(n)  asm volatile("cp.async.wait_group %0;\n" :: "n"(n) : "memory")

__device__ __forceinline__ void ldsm_x4(uint32_t* r, uint32_t addr) {
    asm volatile("ldmatrix.sync.aligned.m8n8.x4.shared.b16 {%0,%1,%2,%3}, [%4];"
        : "=r"(r[0]), "=r"(r[1]), "=r"(r[2]), "=r"(r[3]) : "r"(addr));
}
__device__ __forceinline__ void ldsm_x4t(uint32_t* r, uint32_t addr) {
    asm volatile("ldmatrix.sync.aligned.m8n8.x4.trans.shared.b16 {%0,%1,%2,%3}, [%4];"
        : "=r"(r[0]), "=r"(r[1]), "=r"(r[2]), "=r"(r[3]) : "r"(addr));
}
__device__ __forceinline__ void mma_bf16(float* d, const uint32_t* a, const uint32_t* b) {
    asm volatile(
        "mma.sync.aligned.m16n8k16.row.col.f32.bf16.bf16.f32 "
        "{%0,%1,%2,%3}, {%4,%5,%6,%7}, {%8,%9}, {%0,%1,%2,%3};"
        : "+f"(d[0]), "+f"(d[1]), "+f"(d[2]), "+f"(d[3])
        : "r"(a[0]), "r"(a[1]), "r"(a[2]), "r"(a[3]), "r"(b[0]), "r"(b[1]));
}

// ---------------- smem layout (shared by both mma kernels) ----------------
#define ASTRIDE 80
#define BSTRIDE 272
#define A_TILE  (128 * ASTRIDE)
#define B_TILE  (32 * BSTRIDE)
#define STAGE   (2 * A_TILE + 2 * B_TILE)    // 37888 B
#define MMA_SMEM_TOTAL (2 * STAGE)           // 75776 B
#define OFF_AH  0
#define OFF_AL  A_TILE
#define OFF_BH  (2 * A_TILE)
#define OFF_BL  (2 * A_TILE + B_TILE)

// ----------------------------------------------------------------------------
// Elementwise fp32 -> bf16 hi/lo split
// ----------------------------------------------------------------------------
__global__ void split_kernel(const float* __restrict__ src,
                             __nv_bfloat16* __restrict__ hi,
                             __nv_bfloat16* __restrict__ lo, long count)
{
    long i = (long)blockIdx.x * 1024 + threadIdx.x * 4;
    if (i + 3 >= count) {
        for (long k = i; k < count; k++) {
            float v = src[k];
            __nv_bfloat16 h = __float2bfloat16(v);
            hi[k] = h;
            lo[k] = __float2bfloat16(v - __bfloat162float(h));
        }
        return;
    }
    float4 v4 = *reinterpret_cast<const float4*>(src + i);
    float vs[4] = {v4.x, v4.y, v4.z, v4.w};
    __nv_bfloat16 h4[4], l4[4];
    #pragma unroll
    for (int j = 0; j < 4; j++) {
        h4[j] = __float2bfloat16(vs[j]);
        l4[j] = __float2bfloat16(vs[j] - __bfloat162float(h4[j]));
    }
    *reinterpret_cast<uint2*>(hi + i) = *reinterpret_cast<uint2*>(h4);
    *reinterpret_cast<uint2*>(lo + i) = *reinterpret_cast<uint2*>(l4);
}

// ----------------------------------------------------------------------------
// Transpose u (1024x64) -> uT (64x1024), split hi/lo
// ----------------------------------------------------------------------------
__global__ void transpose_u_split_kernel(const float* __restrict__ u,
                                         __nv_bfloat16* __restrict__ hi,
                                         __nv_bfloat16* __restrict__ lo)
{
    __shared__ float t[32][33];
    int b0 = blockIdx.x * 32;
    int d0 = blockIdx.y * 32;
    int x = threadIdx.x, y = threadIdx.y;
    t[y][x] = u[(long)(b0 + y) * 64 + (d0 + x)];
    __syncthreads();
    float v = t[x][y];
    __nv_bfloat16 h = __float2bfloat16(v);
    hi[(long)(d0 + y) * 1024 + (b0 + x)] = h;
    lo[(long)(d0 + y) * 1024 + (b0 + x)] = __float2bfloat16(v - __bfloat162float(h));
}

// ----------------------------------------------------------------------------
// Build sliding-window A matrix (4096 x 4160) bf16 hi/lo
// ----------------------------------------------------------------------------
__global__ void build_A_kernel(const float* __restrict__ xi,
                               __nv_bfloat16* __restrict__ Ahi,
                               __nv_bfloat16* __restrict__ Alo)
{
    int n = blockIdx.x;
    for (int k = threadIdx.x; k < 4160; k += 256) {
        int m = k / 65;
        int j = k - m * 65;
        float v = xi[m * 4160 + n + j];
        __nv_bfloat16 h = __float2bfloat16(v);
        float lo = v - __bfloat162float(h);
        Ahi[(long)n * 4160 + k] = h;
        Alo[(long)n * 4160 + k] = __float2bfloat16(lo);
    }
}

// ----------------------------------------------------------------------------
// MLP layer: Y[m] = sigmoid(W[m] (rows x K) @ X[m] (K x 1024) + bias[m])
// Split-precision mma.sync; writes Y as bf16 hi/lo.
// CTA tile 128x128, 8 warps (4m x 2n), warp 32x64, K-chunk 32, double-buffer.
// ----------------------------------------------------------------------------
__global__ __launch_bounds__(256) void mlp_mma_kernel(
    const __nv_bfloat16* __restrict__ Whi, const __nv_bfloat16* __restrict__ Wlo,
    long wStride,
    const __nv_bfloat16* __restrict__ Xhi, const __nv_bfloat16* __restrict__ Xlo,
    long xStride,
    const float* __restrict__ bias_all, int biasStride,
    __nv_bfloat16* __restrict__ Yhi, __nv_bfloat16* __restrict__ Ylo,
    long yStride,
    int rows, int K)
{
    extern __shared__ char smem[];
    const uint32_t sb = smem_u32(smem);
    const int tid = threadIdx.x;
    const int lane = tid & 31;
    const int wid = tid >> 5;
    const int wm = wid & 3;
    const int wn = wid >> 2;
    const int m = blockIdx.z;
    const int row0 = blockIdx.y * 128;
    const int col0 = blockIdx.x * 128;

    const __nv_bfloat16* Ah = Whi + (long)m * wStride;
    const __nv_bfloat16* Al = Wlo + (long)m * wStride;
    const __nv_bfloat16* Bh = Xhi + (long)m * xStride;
    const __nv_bfloat16* Bl = Xlo + (long)m * xStride;
    const float* bias = bias_all + (long)m * biasStride;

    float acc[2][8][4];
    #pragma unroll
    for (int mi = 0; mi < 2; mi++)
        #pragma unroll
        for (int nj = 0; nj < 8; nj++)
            #pragma unroll
            for (int q = 0; q < 4; q++) acc[mi][nj][q] = 0.0f;

    const int quad = lane >> 3;
    const int r8 = lane & 7;
    const uint32_t aoff = (wm * 32 + (quad & 1) * 8 + r8) * ASTRIDE + (quad >> 1) * 16;
    const uint32_t boff = ((quad & 1) * 8 + r8) * BSTRIDE + (wn * 64 + (quad >> 1) * 8) * 2;

    const int nChunks = K >> 5;

    // stage loader (A: rows x 32 with row guard; B: 32 x 128)
    auto load = [&](uint32_t sbase, int k0) {
        #pragma unroll
        for (int i = 0; i < 2; i++) {
            int idx = tid + i * 256;
            int r = idx >> 2;
            int c = idx & 3;
            int gr = row0 + r;
            bool ok = gr < rows;
            long g = (long)(ok ? gr : 0) * K + k0 + c * 8;
            uint32_t d = r * ASTRIDE + c * 16;
            cp16z(sbase + OFF_AH + d, Ah + g, ok);
            cp16z(sbase + OFF_AL + d, Al + g, ok);
        }
        #pragma unroll
        for (int i = 0; i < 2; i++) {
            int idx = tid + i * 256;
            int r = idx >> 4;
            int c = idx & 15;
            long g = (long)(k0 + r) * 1024 + col0 + c * 8;
            uint32_t d = r * BSTRIDE + c * 16;
            cp16(sbase + OFF_BH + d, Bh + g);
            cp16(sbase + OFF_BL + d, Bl + g);
        }
    };

    load(sb, 0);
    CP_COMMIT();

    for (int t = 0; t < nChunks; t++) {
        const uint32_t cur = sb + (uint32_t)(t & 1) * STAGE;
        if (t + 1 < nChunks) {
            load(sb + (uint32_t)((t + 1) & 1) * STAGE, (t + 1) * 32);
            CP_COMMIT();
            CP_WAIT(1);
        } else {
            CP_WAIT(0);
        }
        __syncthreads();

        #pragma unroll
        for (int ks = 0; ks < 2; ks++) {
            uint32_t ah[2][4], al[2][4];
            ldsm_x4(ah[0], cur + OFF_AH + aoff + ks * 32);
            ldsm_x4(ah[1], cur + OFF_AH + aoff + 16 * ASTRIDE + ks * 32);
            ldsm_x4(al[0], cur + OFF_AL + aoff + ks * 32);
            ldsm_x4(al[1], cur + OFF_AL + aoff + 16 * ASTRIDE + ks * 32);

            uint32_t bh[8][2], bl[8][2];
            #pragma unroll
            for (int g = 0; g < 4; g++) {
                uint32_t r[4];
                ldsm_x4t(r, cur + OFF_BH + boff + g * 32 + ks * 16 * BSTRIDE);
                bh[2 * g][0] = r[0]; bh[2 * g][1] = r[1];
                bh[2 * g + 1][0] = r[2]; bh[2 * g + 1][1] = r[3];
                ldsm_x4t(r, cur + OFF_BL + boff + g * 32 + ks * 16 * BSTRIDE);
                bl[2 * g][0] = r[0]; bl[2 * g][1] = r[1];
                bl[2 * g + 1][0] = r[2]; bl[2 * g + 1][1] = r[3];
            }

            #pragma unroll
            for (int mi = 0; mi < 2; mi++)
                #pragma unroll
                for (int nj = 0; nj < 8; nj++) {
                    mma_bf16(acc[mi][nj], ah[mi], bh[nj]);
                    mma_bf16(acc[mi][nj], ah[mi], bl[nj]);
                    mma_bf16(acc[mi][nj], al[mi], bh[nj]);
                }
        }
        __syncthreads();
    }

    // epilogue: sigmoid + hi/lo split store
    const int grp = lane >> 2;
    const int qid = lane & 3;
    __nv_bfloat16* yh = Yhi + (long)m * yStride;
    __nv_bfloat16* yl = Ylo + (long)m * yStride;
    #pragma unroll
    for (int mi = 0; mi < 2; mi++) {
        int rbase = row0 + wm * 32 + mi * 16;
        #pragma unroll
        for (int half = 0; half < 2; half++) {
            int gr = rbase + grp + half * 8;
            if (gr >= rows) continue;
            float bv = bias[gr];
            #pragma unroll
            for (int nj = 0; nj < 8; nj++) {
                int cn = col0 + wn * 64 + nj * 8 + qid * 2;
                float y0 = sigmoidf_fast(acc[mi][nj][2 * half + 0] + bv);
                float y1 = sigmoidf_fast(acc[mi][nj][2 * half + 1] + bv);
                __nv_bfloat16 h0 = __float2bfloat16(y0);
                __nv_bfloat16 h1 = __float2bfloat16(y1);
                __nv_bfloat16 l0 = __float2bfloat16(y0 - __bfloat162float(h0));
                __nv_bfloat16 l1 = __float2bfloat16(y1 - __bfloat162float(h1));
                __nv_bfloat162 hp; hp.x = h0; hp.y = h1;
                __nv_bfloat162 lp; lp.x = l0; lp.y = l1;
                *reinterpret_cast<__nv_bfloat162*>(yh + (long)gr * 1024 + cn) = hp;
                *reinterpret_cast<__nv_bfloat162*>(yl + (long)gr * 1024 + cn) = lp;
            }
        }
    }
}

// ----------------------------------------------------------------------------
// Output GEMM (unchanged from round 2):
//   out (4096 x 1024) = A (4096 x 4160) @ B (4160 x 1024)
// ----------------------------------------------------------------------------
__global__ __launch_bounds__(256) void out_mma_kernel(
    const __nv_bfloat16* __restrict__ Ahi, const __nv_bfloat16* __restrict__ Alo,
    const __nv_bfloat16* __restrict__ Bhi, const __nv_bfloat16* __restrict__ Blo,
    float* __restrict__ out)
{
    extern __shared__ char smem[];
    const uint32_t sb = smem_u32(smem);
    const int tid = threadIdx.x;
    const int lane = tid & 31;
    const int wid = tid >> 5;
    const int wm = wid & 3;
    const int wn = wid >> 2;
    const int n0 = blockIdx.y * 128;
    const int col0 = blockIdx.x * 128;

    float acc[2][8][4];
    #pragma unroll
    for (int mi = 0; mi < 2; mi++)
        #pragma unroll
        for (int nj = 0; nj < 8; nj++)
            #pragma unroll
            for (int q = 0; q < 4; q++) acc[mi][nj][q] = 0.0f;

    const int quad = lane >> 3;
    const int r8 = lane & 7;
    const uint32_t aoff = (wm * 32 + (quad & 1) * 8 + r8) * ASTRIDE + (quad >> 1) * 16;
    const uint32_t boff = ((quad & 1) * 8 + r8) * BSTRIDE + (wn * 64 + (quad >> 1) * 8) * 2;

    auto load = [&](uint32_t sbase, int k0) {
        #pragma unroll
        for (int i = 0; i < 2; i++) {
            int idx = tid + i * 256;
            int r = idx >> 2;
            int c = idx & 3;
            long g = (long)(n0 + r) * 4160 + k0 + c * 8;
            uint32_t d = r * ASTRIDE + c * 16;
            cp16(sbase + OFF_AH + d, Ahi + g);
            cp16(sbase + OFF_AL + d, Alo + g);
        }
        #pragma unroll
        for (int i = 0; i < 2; i++) {
            int idx = tid + i * 256;
            int r = idx >> 4;
            int c = idx & 15;
            long g = (long)(k0 + r) * 1024 + col0 + c * 8;
            uint32_t d = r * BSTRIDE + c * 16;
            cp16(sbase + OFF_BH + d, Bhi + g);
            cp16(sbase + OFF_BL + d, Blo + g);
        }
    };

    load(sb, 0);
    CP_COMMIT();

    for (int t = 0; t < 130; t++) {
        const uint32_t cur = sb + (uint32_t)(t & 1) * STAGE;
        if (t + 1 < 130) {
            load(sb + (uint32_t)((t + 1) & 1) * STAGE, (t + 1) * 32);
            CP_COMMIT();
            CP_WAIT(1);
        } else {
            CP_WAIT(0);
        }
        __syncthreads();

        #pragma unroll
        for (int ks = 0; ks < 2; ks++) {
            uint32_t ah[2][4], al[2][4];
            ldsm_x4(ah[0], cur + OFF_AH + aoff + ks * 32);
            ldsm_x4(ah[1], cur + OFF_AH + aoff + 16 * ASTRIDE + ks * 32);
            ldsm_x4(al[0], cur + OFF_AL + aoff + ks * 32);
            ldsm_x4(al[1], cur + OFF_AL + aoff + 16 * ASTRIDE + ks * 32);

            uint32_t bh[8][2], bl[8][2];
            #pragma unroll
            for (int g = 0; g < 4; g++) {
                uint32_t r[4];
                ldsm_x4t(r, cur + OFF_BH + boff + g * 32 + ks * 16 * BSTRIDE);
                bh[2 * g][0] = r[0]; bh[2 * g][1] = r[1];
                bh[2 * g + 1][0] = r[2]; bh[2 * g + 1][1] = r[3];
                ldsm_x4t(r, cur + OFF_BL + boff + g * 32 + ks * 16 * BSTRIDE);
                bl[2 * g][0] = r[0]; bl[2 * g][1] = r[1];
                bl[2 * g + 1][0] = r[2]; bl[2 * g + 1][1] = r[3];
            }

            #pragma unroll
            for (int mi = 0; mi < 2; mi++)
                #pragma unroll
                for (int nj = 0; nj < 8; nj++) {
                    mma_bf16(acc[mi][nj], ah[mi], bh[nj]);
                    mma_bf16(acc[mi][nj], ah[mi], bl[nj]);
                    mma_bf16(acc[mi][nj], al[mi], bh[nj]);
                }
        }
        __syncthreads();
    }

    const int grp = lane >> 2;
    const int qid = lane & 3;
    #pragma unroll
    for (int mi = 0; mi < 2; mi++) {
        int rbase = n0 + wm * 32 + mi * 16;
        #pragma unroll
        for (int nj = 0; nj < 8; nj++) {
            int cn = col0 + wn * 64 + nj * 8 + qid * 2;
            *reinterpret_cast<float2*>(&out[(long)(rbase + grp) * 1024 + cn]) =
                make_float2(acc[mi][nj][0], acc[mi][nj][1]);
            *reinterpret_cast<float2*>(&out[(long)(rbase + grp + 8) * 1024 + cn]) =
                make_float2(acc[mi][nj][2], acc[mi][nj][3]);
        }
    }
}

// ----------------------------------------------------------------------------
// Launch
// ----------------------------------------------------------------------------
extern "C" void kernel_launch(void* const* d_in, const int* in_sizes, int n_in,
                              void* d_out, int out_size) {
    const float* u  = (const float*)d_in[0];
    const float* w0 = (const float*)d_in[1];
    const float* b0 = (const float*)d_in[2];
    const float* w  = (const float*)d_in[3];
    const float* b  = (const float*)d_in[4];
    const float* wf = (const float*)d_in[5];
    const float* bf = (const float*)d_in[6];
    const float* xi = (const float*)d_in[7];
    float* out = (float*)d_out;

    void* p;
    cudaGetSymbolAddress(&p, g_uThi);  __nv_bfloat16* uThi = (__nv_bfloat16*)p;
    cudaGetSymbolAddress(&p, g_uTlo);  __nv_bfloat16* uTlo = (__nv_bfloat16*)p;
    cudaGetSymbolAddress(&p, g_W0hi);  __nv_bfloat16* W0hi = (__nv_bfloat16*)p;
    cudaGetSymbolAddress(&p, g_W0lo);  __nv_bfloat16* W0lo = (__nv_bfloat16*)p;
    cudaGetSymbolAddress(&p, g_Whi);   __nv_bfloat16* Whi  = (__nv_bfloat16*)p;
    cudaGetSymbolAddress(&p, g_Wlo);   __nv_bfloat16* Wlo  = (__nv_bfloat16*)p;
    cudaGetSymbolAddress(&p, g_Wfhi);  __nv_bfloat16* Wfhi = (__nv_bfloat16*)p;
    cudaGetSymbolAddress(&p, g_Wflo);  __nv_bfloat16* Wflo = (__nv_bfloat16*)p;
    cudaGetSymbolAddress(&p, g_actAhi); __nv_bfloat16* aAhi = (__nv_bfloat16*)p;
    cudaGetSymbolAddress(&p, g_actAlo); __nv_bfloat16* aAlo = (__nv_bfloat16*)p;
    cudaGetSymbolAddress(&p, g_actBhi); __nv_bfloat16* aBhi = (__nv_bfloat16*)p;
    cudaGetSymbolAddress(&p, g_actBlo); __nv_bfloat16* aBlo = (__nv_bfloat16*)p;
    cudaGetSymbolAddress(&p, g_Ahi);   __nv_bfloat16* Ahi = (__nv_bfloat16*)p;
    cudaGetSymbolAddress(&p, g_Alo);   __nv_bfloat16* Alo = (__nv_bfloat16*)p;
    cudaGetSymbolAddress(&p, g_Bhi);   __nv_bfloat16* Bhi = (__nv_bfloat16*)p;
    cudaGetSymbolAddress(&p, g_Blo);   __nv_bfloat16* Blo = (__nv_bfloat16*)p;

    cudaFuncSetAttribute(mlp_mma_kernel,
                         cudaFuncAttributeMaxDynamicSharedMemorySize, MMA_SMEM_TOTAL);
    cudaFuncSetAttribute(out_mma_kernel,
                         cudaFuncAttributeMaxDynamicSharedMemorySize, MMA_SMEM_TOTAL);

    // ---- precompute: splits + sliding-window A ----
    build_A_kernel<<<4096, 256>>>(xi, Ahi, Alo);
    {
        long c0 = 64L * 256 * 64;
        split_kernel<<<(unsigned)((c0 + 1023) / 1024), 256>>>(w0, W0hi, W0lo, c0);
        long c1 = 3L * 64 * 256 * 256;
        split_kernel<<<(unsigned)((c1 + 1023) / 1024), 256>>>(w, Whi, Wlo, c1);
        long c2 = 64L * 65 * 256;
        split_kernel<<<(unsigned)((c2 + 1023) / 1024), 256>>>(wf, Wfhi, Wflo, c2);
    }
    transpose_u_split_kernel<<<dim3(32, 2), dim3(32, 32)>>>(u, uThi, uTlo);

    // ---- MLP chain ----
    // layer 0: rows=256, K=64, X = uT (shared across m: xStride=0)
    mlp_mma_kernel<<<dim3(8, 2, 64), 256, MMA_SMEM_TOTAL>>>(
        W0hi, W0lo, 256L * 64, uThi, uTlo, 0L, b0, 256,
        aAhi, aAlo, 256L * 1024, 256, 64);

    // 3 hidden layers: rows=256, K=256
    const __nv_bfloat16* sh = aAhi; const __nv_bfloat16* sl = aAlo;
    __nv_bfloat16* dh = aBhi; __nv_bfloat16* dl = aBlo;
    for (int i = 0; i < 3; i++) {
        mlp_mma_kernel<<<dim3(8, 2, 64), 256, MMA_SMEM_TOTAL>>>(
            Whi + (long)i * 64 * 256 * 256, Wlo + (long)i * 64 * 256 * 256,
            256L * 256, sh, sl, 256L * 1024,
            b + (long)i * 64 * 256, 256,
            dh, dl, 256L * 1024, 256, 256);
        const __nv_bfloat16* th = sh; const __nv_bfloat16* tl = sl;
        sh = dh; sl = dl;
        dh = (__nv_bfloat16*)th; dl = (__nv_bfloat16*)tl;
    }

    // final layer: rows=65, K=256 -> writes B operand (4160 x 1024) directly
    mlp_mma_kernel<<<dim3(8, 1, 64), 256, MMA_SMEM_TOTAL>>>(
        Wfhi, Wflo, 65L * 256, sh, sl, 256L * 1024, bf, 65,
        Bhi, Blo, 65L * 1024, 65, 256);

    // ---- output GEMM ----
    out_mma_kernel<<<dim3(8, 32), 256, MMA_SMEM_TOTAL>>>(Ahi, Alo, Bhi, Blo, out);
}

// round 6
// speedup vs baseline: 2.8262x; 1.0356x over previous
#include <cuda_runtime.h>
#include <cuda_bf16.h>
#include <cstdint>

// ============================================================================
// spectralNNDeepshared2 — Round 5:
//   bf16 split-precision mma.sync everywhere (round-3 structure), plus:
//     - __launch_bounds__(256, 2): force <=128 regs -> 2 CTAs/SM
//     - 3-stage cp.async ring, ONE __syncthreads per K-chunk
//     - MMA terms issued in 3 independent passes (no 3-deep RAW chains)
// ============================================================================

// ---------------- scratch ----------------
__device__ __nv_bfloat16 g_uThi[64 * 1024];
__device__ __nv_bfloat16 g_uTlo[64 * 1024];
__device__ __nv_bfloat16 g_W0hi[64 * 256 * 64];
__device__ __nv_bfloat16 g_W0lo[64 * 256 * 64];
__device__ __nv_bfloat16 g_Whi[3L * 64 * 256 * 256];
__device__ __nv_bfloat16 g_Wlo[3L * 64 * 256 * 256];
__device__ __nv_bfloat16 g_Wfhi[64 * 65 * 256];
__device__ __nv_bfloat16 g_Wflo[64 * 65 * 256];
__device__ __nv_bfloat16 g_actAhi[64L * 256 * 1024];
__device__ __nv_bfloat16 g_actAlo[64L * 256 * 1024];
__device__ __nv_bfloat16 g_actBhi[64L * 256 * 1024];
__device__ __nv_bfloat16 g_actBlo[64L * 256 * 1024];
__device__ __nv_bfloat16 g_Ahi[4096L * 4160];
__device__ __nv_bfloat16 g_Alo[4096L * 4160];
__device__ __nv_bfloat16 g_Bhi[4160L * 1024];
__device__ __nv_bfloat16 g_Blo[4160L * 1024];

__device__ __forceinline__ float sigmoidf_fast(float x) {
    return 1.0f / (1.0f + __expf(-x));
}
__device__ __forceinline__ uint32_t smem_u32(const void* p) {
    uint32_t a;
    asm("{ .reg .u64 t; cvta.to.shared.u64 t, %1; cvt.u32.u64 %0, t; }"
        : "=r"(a) : "l"(p));
    return a;
}

// ---------------- cp.async / ldmatrix / mma helpers ----------------
__device__ __forceinline__ void cp16(uint32_t dst, const void* src) {
    asm volatile("cp.async.cg.shared.global [%0], [%1], 16;\n"
                 :: "r"(dst), "l"(src));
}
__device__ __forceinline__ void cp16z(uint32_t dst, const void* src, bool valid) {
    int sz = valid ? 16 : 0;
    asm volatile("cp.async.cg.shared.global [%0], [%1], 16, %2;\n"
                 :: "r"(dst), "l"(src), "r"(sz));
}
#define CP_COMMIT() asm volatile("cp.async.commit_group;\n" ::: "memory")
#define CP_WAIT(n)  asm volatile("cp.async.wait_group %0;\n" :: "n"(n) : "memory")

__device__ __forceinline__ void ldsm_x4(uint32_t* r, uint32_t addr) {
    asm volatile("ldmatrix.sync.aligned.m8n8.x4.shared.b16 {%0,%1,%2,%3}, [%4];"
        : "=r"(r[0]), "=r"(r[1]), "=r"(r[2]), "=r"(r[3]) : "r"(addr));
}
__device__ __forceinline__ void ldsm_x4t(uint32_t* r, uint32_t addr) {
    asm volatile("ldmatrix.sync.aligned.m8n8.x4.trans.shared.b16 {%0,%1,%2,%3}, [%4];"
        : "=r"(r[0]), "=r"(r[1]), "=r"(r[2]), "=r"(r[3]) : "r"(addr));
}
__device__ __forceinline__ void mma_bf16(float* d, const uint32_t* a, const uint32_t* b) {
    asm volatile(
        "mma.sync.aligned.m16n8k16.row.col.f32.bf16.bf16.f32 "
        "{%0,%1,%2,%3}, {%4,%5,%6,%7}, {%8,%9}, {%0,%1,%2,%3};"
        : "+f"(d[0]), "+f"(d[1]), "+f"(d[2]), "+f"(d[3])
        : "r"(a[0]), "r"(a[1]), "r"(a[2]), "r"(a[3]), "r"(b[0]), "r"(b[1]));
}

// ---------------- smem layout ----------------
#define ASTRIDE 80
#define BSTRIDE 272
#define A_TILE  (128 * ASTRIDE)
#define B_TILE  (32 * BSTRIDE)
#define STAGE   (2 * A_TILE + 2 * B_TILE)    // 37888 B
#define NSTAGES 3
#define MMA_SMEM_TOTAL (NSTAGES * STAGE)     // 113664 B (2 CTAs/SM: 227 KB)
#define OFF_AH  0
#define OFF_AL  A_TILE
#define OFF_BH  (2 * A_TILE)
#define OFF_BL  (2 * A_TILE + B_TILE)

// ----------------------------------------------------------------------------
// Elementwise fp32 -> bf16 hi/lo split
// ----------------------------------------------------------------------------
__global__ void split_kernel(const float* __restrict__ src,
                             __nv_bfloat16* __restrict__ hi,
                             __nv_bfloat16* __restrict__ lo, long count)
{
    long i = (long)blockIdx.x * 1024 + threadIdx.x * 4;
    if (i + 3 >= count) {
        for (long k = i; k < count; k++) {
            float v = src[k];
            __nv_bfloat16 h = __float2bfloat16(v);
            hi[k] = h;
            lo[k] = __float2bfloat16(v - __bfloat162float(h));
        }
        return;
    }
    float4 v4 = *reinterpret_cast<const float4*>(src + i);
    float vs[4] = {v4.x, v4.y, v4.z, v4.w};
    __nv_bfloat16 h4[4], l4[4];
    #pragma unroll
    for (int j = 0; j < 4; j++) {
        h4[j] = __float2bfloat16(vs[j]);
        l4[j] = __float2bfloat16(vs[j] - __bfloat162float(h4[j]));
    }
    *reinterpret_cast<uint2*>(hi + i) = *reinterpret_cast<uint2*>(h4);
    *reinterpret_cast<uint2*>(lo + i) = *reinterpret_cast<uint2*>(l4);
}

// ----------------------------------------------------------------------------
// Transpose u (1024x64) -> uT (64x1024), split hi/lo
// ----------------------------------------------------------------------------
__global__ void transpose_u_split_kernel(const float* __restrict__ u,
                                         __nv_bfloat16* __restrict__ hi,
                                         __nv_bfloat16* __restrict__ lo)
{
    __shared__ float t[32][33];
    int b0 = blockIdx.x * 32;
    int d0 = blockIdx.y * 32;
    int x = threadIdx.x, y = threadIdx.y;
    t[y][x] = u[(long)(b0 + y) * 64 + (d0 + x)];
    __syncthreads();
    float v = t[x][y];
    __nv_bfloat16 h = __float2bfloat16(v);
    hi[(long)(d0 + y) * 1024 + (b0 + x)] = h;
    lo[(long)(d0 + y) * 1024 + (b0 + x)] = __float2bfloat16(v - __bfloat162float(h));
}

// ----------------------------------------------------------------------------
// Build sliding-window A matrix (4096 x 4160) bf16 hi/lo
// ----------------------------------------------------------------------------
__global__ void build_A_kernel(const float* __restrict__ xi,
                               __nv_bfloat16* __restrict__ Ahi,
                               __nv_bfloat16* __restrict__ Alo)
{
    int n = blockIdx.x;
    for (int k = threadIdx.x; k < 4160; k += 256) {
        int m = k / 65;
        int j = k - m * 65;
        float v = xi[m * 4160 + n + j];
        __nv_bfloat16 h = __float2bfloat16(v);
        float lo = v - __bfloat162float(h);
        Ahi[(long)n * 4160 + k] = h;
        Alo[(long)n * 4160 + k] = __float2bfloat16(lo);
    }
}

// ----------------------------------------------------------------------------
// MLP layer: Y[m] = sigmoid(W[m] (rows x K) @ X[m] (K x 1024) + bias[m])
// 3-stage ring, single sync per chunk, 3-pass MMA ordering.
// ----------------------------------------------------------------------------
__global__ __launch_bounds__(256, 2) void mlp_mma_kernel(
    const __nv_bfloat16* __restrict__ Whi, const __nv_bfloat16* __restrict__ Wlo,
    long wStride,
    const __nv_bfloat16* __restrict__ Xhi, const __nv_bfloat16* __restrict__ Xlo,
    long xStride,
    const float* __restrict__ bias_all, int biasStride,
    __nv_bfloat16* __restrict__ Yhi, __nv_bfloat16* __restrict__ Ylo,
    long yStride,
    int rows, int K)
{
    extern __shared__ char smem[];
    const uint32_t sb = smem_u32(smem);
    const int tid = threadIdx.x;
    const int lane = tid & 31;
    const int wid = tid >> 5;
    const int wm = wid & 3;
    const int wn = wid >> 2;
    const int m = blockIdx.z;
    const int row0 = blockIdx.y * 128;
    const int col0 = blockIdx.x * 128;

    const __nv_bfloat16* Ah = Whi + (long)m * wStride;
    const __nv_bfloat16* Al = Wlo + (long)m * wStride;
    const __nv_bfloat16* Bh = Xhi + (long)m * xStride;
    const __nv_bfloat16* Bl = Xlo + (long)m * xStride;
    const float* bias = bias_all + (long)m * biasStride;

    float acc[2][8][4];
    #pragma unroll
    for (int mi = 0; mi < 2; mi++)
        #pragma unroll
        for (int nj = 0; nj < 8; nj++)
            #pragma unroll
            for (int q = 0; q < 4; q++) acc[mi][nj][q] = 0.0f;

    const int quad = lane >> 3;
    const int r8 = lane & 7;
    const uint32_t aoff = (wm * 32 + (quad & 1) * 8 + r8) * ASTRIDE + (quad >> 1) * 16;
    const uint32_t boff = ((quad & 1) * 8 + r8) * BSTRIDE + (wn * 64 + (quad >> 1) * 8) * 2;

    const int nChunks = K >> 5;

    auto load = [&](int stageIdx, int k0) {
        uint32_t sbase = sb + (uint32_t)stageIdx * STAGE;
        #pragma unroll
        for (int i = 0; i < 2; i++) {
            int idx = tid + i * 256;
            int r = idx >> 2;
            int c = idx & 3;
            int gr = row0 + r;
            bool ok = gr < rows;
            long g = (long)(ok ? gr : 0) * K + k0 + c * 8;
            uint32_t d = r * ASTRIDE + c * 16;
            cp16z(sbase + OFF_AH + d, Ah + g, ok);
            cp16z(sbase + OFF_AL + d, Al + g, ok);
        }
        #pragma unroll
        for (int i = 0; i < 2; i++) {
            int idx = tid + i * 256;
            int r = idx >> 4;
            int c = idx & 15;
            long g = (long)(k0 + r) * 1024 + col0 + c * 8;
            uint32_t d = r * BSTRIDE + c * 16;
            cp16(sbase + OFF_BH + d, Bh + g);
            cp16(sbase + OFF_BL + d, Bl + g);
        }
    };

    load(0, 0);
    CP_COMMIT();
    if (nChunks > 1) load(1, 32);
    CP_COMMIT();

    int curStage = 0, nxtStage = 2;
    for (int t = 0; t < nChunks; t++) {
        CP_WAIT(1);
        __syncthreads();
        if (t + 2 < nChunks) load(nxtStage, (t + 2) * 32);
        CP_COMMIT();

        const uint32_t cur = sb + (uint32_t)curStage * STAGE;
        curStage = (curStage == NSTAGES - 1) ? 0 : curStage + 1;
        nxtStage = (nxtStage == NSTAGES - 1) ? 0 : nxtStage + 1;

        #pragma unroll
        for (int ks = 0; ks < 2; ks++) {
            uint32_t ah[2][4], al[2][4];
            ldsm_x4(ah[0], cur + OFF_AH + aoff + ks * 32);
            ldsm_x4(ah[1], cur + OFF_AH + aoff + 16 * ASTRIDE + ks * 32);
            ldsm_x4(al[0], cur + OFF_AL + aoff + ks * 32);
            ldsm_x4(al[1], cur + OFF_AL + aoff + 16 * ASTRIDE + ks * 32);

            uint32_t bh[8][2], bl[8][2];
            #pragma unroll
            for (int g = 0; g < 4; g++) {
                uint32_t r[4];
                ldsm_x4t(r, cur + OFF_BH + boff + g * 32 + ks * 16 * BSTRIDE);
                bh[2 * g][0] = r[0]; bh[2 * g][1] = r[1];
                bh[2 * g + 1][0] = r[2]; bh[2 * g + 1][1] = r[3];
                ldsm_x4t(r, cur + OFF_BL + boff + g * 32 + ks * 16 * BSTRIDE);
                bl[2 * g][0] = r[0]; bl[2 * g][1] = r[1];
                bl[2 * g + 1][0] = r[2]; bl[2 * g + 1][1] = r[3];
            }

            // three independent passes: no 3-deep RAW chains on acc
            #pragma unroll
            for (int mi = 0; mi < 2; mi++)
                #pragma unroll
                for (int nj = 0; nj < 8; nj++) mma_bf16(acc[mi][nj], ah[mi], bh[nj]);
            #pragma unroll
            for (int mi = 0; mi < 2; mi++)
                #pragma unroll
                for (int nj = 0; nj < 8; nj++) mma_bf16(acc[mi][nj], ah[mi], bl[nj]);
            #pragma unroll
            for (int mi = 0; mi < 2; mi++)
                #pragma unroll
                for (int nj = 0; nj < 8; nj++) mma_bf16(acc[mi][nj], al[mi], bh[nj]);
        }
        __syncthreads();
    }

    // epilogue: sigmoid + hi/lo split store
    const int grp = lane >> 2;
    const int qid = lane & 3;
    __nv_bfloat16* yh = Yhi + (long)m * yStride;
    __nv_bfloat16* yl = Ylo + (long)m * yStride;
    #pragma unroll
    for (int mi = 0; mi < 2; mi++) {
        int rbase = row0 + wm * 32 + mi * 16;
        #pragma unroll
        for (int half = 0; half < 2; half++) {
            int gr = rbase + grp + half * 8;
            if (gr >= rows) continue;
            float bv = bias[gr];
            #pragma unroll
            for (int nj = 0; nj < 8; nj++) {
                int cn = col0 + wn * 64 + nj * 8 + qid * 2;
                float y0 = sigmoidf_fast(acc[mi][nj][2 * half + 0] + bv);
                float y1 = sigmoidf_fast(acc[mi][nj][2 * half + 1] + bv);
                __nv_bfloat16 h0 = __float2bfloat16(y0);
                __nv_bfloat16 h1 = __float2bfloat16(y1);
                __nv_bfloat16 l0 = __float2bfloat16(y0 - __bfloat162float(h0));
                __nv_bfloat16 l1 = __float2bfloat16(y1 - __bfloat162float(h1));
                __nv_bfloat162 hp; hp.x = h0; hp.y = h1;
                __nv_bfloat162 lp; lp.x = l0; lp.y = l1;
                *reinterpret_cast<__nv_bfloat162*>(yh + (long)gr * 1024 + cn) = hp;
                *reinterpret_cast<__nv_bfloat162*>(yl + (long)gr * 1024 + cn) = lp;
            }
        }
    }
}

// ----------------------------------------------------------------------------
// Output GEMM: out (4096 x 1024) = A (4096 x 4160) @ B (4160 x 1024)
// Same 3-stage single-sync pipeline.
// ----------------------------------------------------------------------------
__global__ __launch_bounds__(256, 2) void out_mma_kernel(
    const __nv_bfloat16* __restrict__ Ahi, const __nv_bfloat16* __restrict__ Alo,
    const __nv_bfloat16* __restrict__ Bhi, const __nv_bfloat16* __restrict__ Blo,
    float* __restrict__ out)
{
    extern __shared__ char smem[];
    const uint32_t sb = smem_u32(smem);
    const int tid = threadIdx.x;
    const int lane = tid & 31;
    const int wid = tid >> 5;
    const int wm = wid & 3;
    const int wn = wid >> 2;
    const int n0 = blockIdx.y * 128;
    const int col0 = blockIdx.x * 128;

    float acc[2][8][4];
    #pragma unroll
    for (int mi = 0; mi < 2; mi++)
        #pragma unroll
        for (int nj = 0; nj < 8; nj++)
            #pragma unroll
            for (int q = 0; q < 4; q++) acc[mi][nj][q] = 0.0f;

    const int quad = lane >> 3;
    const int r8 = lane & 7;
    const uint32_t aoff = (wm * 32 + (quad & 1) * 8 + r8) * ASTRIDE + (quad >> 1) * 16;
    const uint32_t boff = ((quad & 1) * 8 + r8) * BSTRIDE + (wn * 64 + (quad >> 1) * 8) * 2;

    auto load = [&](int stageIdx, int k0) {
        uint32_t sbase = sb + (uint32_t)stageIdx * STAGE;
        #pragma unroll
        for (int i = 0; i < 2; i++) {
            int idx = tid + i * 256;
            int r = idx >> 2;
            int c = idx & 3;
            long g = (long)(n0 + r) * 4160 + k0 + c * 8;
            uint32_t d = r * ASTRIDE + c * 16;
            cp16(sbase + OFF_AH + d, Ahi + g);
            cp16(sbase + OFF_AL + d, Alo + g);
        }
        #pragma unroll
        for (int i = 0; i < 2; i++) {
            int idx = tid + i * 256;
            int r = idx >> 4;
            int c = idx & 15;
            long g = (long)(k0 + r) * 1024 + col0 + c * 8;
            uint32_t d = r * BSTRIDE + c * 16;
            cp16(sbase + OFF_BH + d, Bhi + g);
            cp16(sbase + OFF_BL + d, Blo + g);
        }
    };

    load(0, 0);
    CP_COMMIT();
    load(1, 32);
    CP_COMMIT();

    int curStage = 0, nxtStage = 2;
    for (int t = 0; t < 130; t++) {
        CP_WAIT(1);
        __syncthreads();
        if (t + 2 < 130) load(nxtStage, (t + 2) * 32);
        CP_COMMIT();

        const uint32_t cur = sb + (uint32_t)curStage * STAGE;
        curStage = (curStage == NSTAGES - 1) ? 0 : curStage + 1;
        nxtStage = (nxtStage == NSTAGES - 1) ? 0 : nxtStage + 1;

        #pragma unroll
        for (int ks = 0; ks < 2; ks++) {
            uint32_t ah[2][4], al[2][4];
            ldsm_x4(ah[0], cur + OFF_AH + aoff + ks * 32);
            ldsm_x4(ah[1], cur + OFF_AH + aoff + 16 * ASTRIDE + ks * 32);
            ldsm_x4(al[0], cur + OFF_AL + aoff + ks * 32);
            ldsm_x4(al[1], cur + OFF_AL + aoff + 16 * ASTRIDE + ks * 32);

            uint32_t bh[8][2], bl[8][2];
            #pragma unroll
            for (int g = 0; g < 4; g++) {
                uint32_t r[4];
                ldsm_x4t(r, cur + OFF_BH + boff + g * 32 + ks * 16 * BSTRIDE);
                bh[2 * g][0] = r[0]; bh[2 * g][1] = r[1];
                bh[2 * g + 1][0] = r[2]; bh[2 * g + 1][1] = r[3];
                ldsm_x4t(r, cur + OFF_BL + boff + g * 32 + ks * 16 * BSTRIDE);
                bl[2 * g][0] = r[0]; bl[2 * g][1] = r[1];
                bl[2 * g + 1][0] = r[2]; bl[2 * g + 1][1] = r[3];
            }

            #pragma unroll
            for (int mi = 0; mi < 2; mi++)
                #pragma unroll
                for (int nj = 0; nj < 8; nj++) mma_bf16(acc[mi][nj], ah[mi], bh[nj]);
            #pragma unroll
            for (int mi = 0; mi < 2; mi++)
                #pragma unroll
                for (int nj = 0; nj < 8; nj++) mma_bf16(acc[mi][nj], ah[mi], bl[nj]);
            #pragma unroll
            for (int mi = 0; mi < 2; mi++)
                #pragma unroll
                for (int nj = 0; nj < 8; nj++) mma_bf16(acc[mi][nj], al[mi], bh[nj]);
        }
        __syncthreads();
    }

    const int grp = lane >> 2;
    const int qid = lane & 3;
    #pragma unroll
    for (int mi = 0; mi < 2; mi++) {
        int rbase = n0 + wm * 32 + mi * 16;
        #pragma unroll
        for (int nj = 0; nj < 8; nj++) {
            int cn = col0 + wn * 64 + nj * 8 + qid * 2;
            *reinterpret_cast<float2*>(&out[(long)(rbase + grp) * 1024 + cn]) =
                make_float2(acc[mi][nj][0], acc[mi][nj][1]);
            *reinterpret_cast<float2*>(&out[(long)(rbase + grp + 8) * 1024 + cn]) =
                make_float2(acc[mi][nj][2], acc[mi][nj][3]);
        }
    }
}

// ----------------------------------------------------------------------------
// Launch
// ----------------------------------------------------------------------------
extern "C" void kernel_launch(void* const* d_in, const int* in_sizes, int n_in,
                              void* d_out, int out_size) {
    const float* u  = (const float*)d_in[0];
    const float* w0 = (const float*)d_in[1];
    const float* b0 = (const float*)d_in[2];
    const float* w  = (const float*)d_in[3];
    const float* b  = (const float*)d_in[4];
    const float* wf = (const float*)d_in[5];
    const float* bf = (const float*)d_in[6];
    const float* xi = (const float*)d_in[7];
    float* out = (float*)d_out;

    void* p;
    cudaGetSymbolAddress(&p, g_uThi);  __nv_bfloat16* uThi = (__nv_bfloat16*)p;
    cudaGetSymbolAddress(&p, g_uTlo);  __nv_bfloat16* uTlo = (__nv_bfloat16*)p;
    cudaGetSymbolAddress(&p, g_W0hi);  __nv_bfloat16* W0hi = (__nv_bfloat16*)p;
    cudaGetSymbolAddress(&p, g_W0lo);  __nv_bfloat16* W0lo = (__nv_bfloat16*)p;
    cudaGetSymbolAddress(&p, g_Whi);   __nv_bfloat16* Whi  = (__nv_bfloat16*)p;
    cudaGetSymbolAddress(&p, g_Wlo);   __nv_bfloat16* Wlo  = (__nv_bfloat16*)p;
    cudaGetSymbolAddress(&p, g_Wfhi);  __nv_bfloat16* Wfhi = (__nv_bfloat16*)p;
    cudaGetSymbolAddress(&p, g_Wflo);  __nv_bfloat16* Wflo = (__nv_bfloat16*)p;
    cudaGetSymbolAddress(&p, g_actAhi); __nv_bfloat16* aAhi = (__nv_bfloat16*)p;
    cudaGetSymbolAddress(&p, g_actAlo); __nv_bfloat16* aAlo = (__nv_bfloat16*)p;
    cudaGetSymbolAddress(&p, g_actBhi); __nv_bfloat16* aBhi = (__nv_bfloat16*)p;
    cudaGetSymbolAddress(&p, g_actBlo); __nv_bfloat16* aBlo = (__nv_bfloat16*)p;
    cudaGetSymbolAddress(&p, g_Ahi);   __nv_bfloat16* Ahi = (__nv_bfloat16*)p;
    cudaGetSymbolAddress(&p, g_Alo);   __nv_bfloat16* Alo = (__nv_bfloat16*)p;
    cudaGetSymbolAddress(&p, g_Bhi);   __nv_bfloat16* Bhi = (__nv_bfloat16*)p;
    cudaGetSymbolAddress(&p, g_Blo);   __nv_bfloat16* Blo = (__nv_bfloat16*)p;

    cudaFuncSetAttribute(mlp_mma_kernel,
                         cudaFuncAttributeMaxDynamicSharedMemorySize, MMA_SMEM_TOTAL);
    cudaFuncSetAttribute(out_mma_kernel,
                         cudaFuncAttributeMaxDynamicSharedMemorySize, MMA_SMEM_TOTAL);

    // ---- precompute: splits + sliding-window A ----
    build_A_kernel<<<4096, 256>>>(xi, Ahi, Alo);
    {
        long c0 = 64L * 256 * 64;
        split_kernel<<<(unsigned)((c0 + 1023) / 1024), 256>>>(w0, W0hi, W0lo, c0);
        long c1 = 3L * 64 * 256 * 256;
        split_kernel<<<(unsigned)((c1 + 1023) / 1024), 256>>>(w, Whi, Wlo, c1);
        long c2 = 64L * 65 * 256;
        split_kernel<<<(unsigned)((c2 + 1023) / 1024), 256>>>(wf, Wfhi, Wflo, c2);
    }
    transpose_u_split_kernel<<<dim3(32, 2), dim3(32, 32)>>>(u, uThi, uTlo);

    // ---- MLP chain ----
    mlp_mma_kernel<<<dim3(8, 2, 64), 256, MMA_SMEM_TOTAL>>>(
        W0hi, W0lo, 256L * 64, uThi, uTlo, 0L, b0, 256,
        aAhi, aAlo, 256L * 1024, 256, 64);

    const __nv_bfloat16* sh = aAhi; const __nv_bfloat16* sl = aAlo;
    __nv_bfloat16* dh = aBhi; __nv_bfloat16* dl = aBlo;
    for (int i = 0; i < 3; i++) {
        mlp_mma_kernel<<<dim3(8, 2, 64), 256, MMA_SMEM_TOTAL>>>(
            Whi + (long)i * 64 * 256 * 256, Wlo + (long)i * 64 * 256 * 256,
            256L * 256, sh, sl, 256L * 1024,
            b + (long)i * 64 * 256, 256,
            dh, dl, 256L * 1024, 256, 256);
        const __nv_bfloat16* th = sh; const __nv_bfloat16* tl = sl;
        sh = dh; sl = dl;
        dh = (__nv_bfloat16*)th; dl = (__nv_bfloat16*)tl;
    }

    // final layer: rows=65, writes out-GEMM B operand directly
    mlp_mma_kernel<<<dim3(8, 1, 64), 256, MMA_SMEM_TOTAL>>>(
        Wfhi, Wflo, 65L * 256, sh, sl, 256L * 1024, bf, 65,
        Bhi, Blo, 65L * 1024, 65, 256);

    // ---- output GEMM ----
    out_mma_kernel<<<dim3(8, 32), 256, MMA_SMEM_TOTAL>>>(Ahi, Alo, Bhi, Blo, out);
}